// round 1
// baseline (speedup 1.0000x reference)
#include <cuda_runtime.h>
#include <cuda_bf16.h>

#define BB 2048
#define TT 512
#define KK 32

// One warp per batch item. lane = current tag k.
// Registers: tc[j] = trans[j][k] (column k), ec[j] = exp(trans[j][k]).
// Per step t (only t < len; masked steps are identity and skipped):
//   Viterbi:  best_k = max_j (aV_j + tc[j]),  bp = first argmax j
//   Forward:  aF_k   = pot + m + log( sum_j exp(aF_j - m) * ec[j] ),  m = max_j aF_j
// Backpointers in shared memory (uint8, 16KB). Backtrace from smem.
__global__ __launch_bounds__(32) void crf_kernel(
    const float* __restrict__ pot,     // [B,T,K]
    const float* __restrict__ trans,   // [K,K]
    const int*   __restrict__ lens,    // [B]
    const int*   __restrict__ tagidx,  // [B,T]
    float*       __restrict__ out)     // [B*T] tags, [B] best, [B] loglik
{
    const int b    = blockIdx.x;
    const int lane = threadIdx.x;

    __shared__ unsigned char bp_sm[TT * KK];   // bp_sm[t*32 + k], valid for 1 <= t < len
    __shared__ float aVbuf[2][KK];
    __shared__ float pFbuf[2][KK];

    // transitions column k into registers (coalesced loads: lane k reads trans[j*32+k])
    float tc[KK], ec[KK];
#pragma unroll
    for (int j = 0; j < KK; j++) {
        float v = trans[j * KK + lane];
        tc[j] = v;
        ec[j] = __expf(v);
    }

    const int len = lens[b];
    const float* pb = pot + (size_t)b * TT * KK;

    float aV = pb[lane];   // Viterbi alpha
    float aF = aV;         // forward alpha

    float pot_next = pb[KK + lane];   // prefetch t=1 (T>=2 always)

    for (int t = 1; t < len; t++) {
        float pt = pot_next;
        int tn = (t + 1 < TT) ? (t + 1) : t;
        pot_next = pb[tn * KK + lane];

        // warp max of forward alpha
        float mF = aF;
#pragma unroll
        for (int s = 16; s; s >>= 1)
            mF = fmaxf(mF, __shfl_xor_sync(0xffffffffu, mF, s));
        float pexp = __expf(aF - mF);

        const int buf = t & 1;
        aVbuf[buf][lane] = aV;
        pFbuf[buf][lane] = pexp;
        __syncwarp();

        const float4* a4 = (const float4*)aVbuf[buf];
        const float4* p4 = (const float4*)pFbuf[buf];

        float b0 = -3.4e38f, b1 = -3.4e38f, b2 = -3.4e38f, b3 = -3.4e38f;
        float s0 = 0.f, s1 = 0.f, s2 = 0.f, s3 = 0.f;
#pragma unroll
        for (int q = 0; q < 8; q++) {
            float4 a = a4[q];
            b0 = fmaxf(b0, a.x + tc[4*q + 0]);
            b1 = fmaxf(b1, a.y + tc[4*q + 1]);
            b2 = fmaxf(b2, a.z + tc[4*q + 2]);
            b3 = fmaxf(b3, a.w + tc[4*q + 3]);
            float4 p = p4[q];
            s0 += p.x * ec[4*q + 0];
            s1 += p.y * ec[4*q + 1];
            s2 += p.z * ec[4*q + 2];
            s3 += p.w * ec[4*q + 3];
        }
        float best = fmaxf(fmaxf(b0, b1), fmaxf(b2, b3));
        float ssum = (s0 + s1) + (s2 + s3);

        // first index achieving the max (matches jnp.argmax tie-breaking)
        int g0 = 63, g1 = 63, g2 = 63, g3 = 63;
#pragma unroll
        for (int q = 0; q < 8; q++) {
            float4 a = a4[q];
            g0 = min(g0, (a.x + tc[4*q + 0] == best) ? (4*q + 0) : 63);
            g1 = min(g1, (a.y + tc[4*q + 1] == best) ? (4*q + 1) : 63);
            g2 = min(g2, (a.z + tc[4*q + 2] == best) ? (4*q + 2) : 63);
            g3 = min(g3, (a.w + tc[4*q + 3] == best) ? (4*q + 3) : 63);
        }
        int arg = min(min(g0, g1), min(g2, g3));

        aV = pt + best;
        aF = pt + mF + __logf(ssum);
        bp_sm[t * KK + lane] = (unsigned char)arg;
    }
    __syncwarp();

    // ---- Viterbi terminal: best_score + last_tag (first max index) ----
    float mv = aV;
#pragma unroll
    for (int s = 16; s; s >>= 1)
        mv = fmaxf(mv, __shfl_xor_sync(0xffffffffu, mv, s));
    unsigned msk = __ballot_sync(0xffffffffu, aV == mv);
    int last_tag = __ffs(msk) - 1;

    // ---- log partition: logsumexp over final forward alpha ----
    float mf = aF;
#pragma unroll
    for (int s = 16; s; s >>= 1)
        mf = fmaxf(mf, __shfl_xor_sync(0xffffffffu, mf, s));
    float ex = __expf(aF - mf);
#pragma unroll
    for (int s = 16; s; s >>= 1)
        ex += __shfl_xor_sync(0xffffffffu, ex, s);
    float log_norm = mf + __logf(ex);

    // ---- decode tags output ----
    // padded tail (t >= len-1) is last_tag (identity backpointers in reference)
    float* otags = out + (size_t)b * TT;
    for (int t = lane; t < TT; t += 32)
        if (t >= len - 1)
            otags[t] = (float)last_tag;

    if (lane == 0) {
        int tg = last_tag;
        for (int t = len - 1; t >= 1; t--) {
            tg = bp_sm[t * KK + tg];
            otags[t - 1] = (float)tg;
        }
    }

    // ---- gold sequence score ----
    const int* ti = tagidx + (size_t)b * TT;
    float acc = 0.f;
    for (int t = lane; t < TT; t += 32) {
        int tg = ti[t];
        if (t < len)
            acc += pb[t * KK + tg];
        if (t < len - 1)
            acc += trans[tg * KK + ti[t + 1]];
    }
#pragma unroll
    for (int s = 16; s; s >>= 1)
        acc += __shfl_xor_sync(0xffffffffu, acc, s);

    if (lane == 0) {
        out[(size_t)BB * TT + b]      = mv;               // best_score
        out[(size_t)BB * TT + BB + b] = acc - log_norm;   // log_likelihood
    }
}

extern "C" void kernel_launch(void* const* d_in, const int* in_sizes, int n_in,
                              void* d_out, int out_size) {
    // Map inputs by element count (sizes are all distinct):
    //   potentials  B*T*K = 33554432 (f32)
    //   transitions K*K   = 1024     (f32)
    //   seq_lengths B     = 2048     (i32)
    //   tag_indices B*T   = 1048576  (i32)
    const float* pot = nullptr;
    const float* trn = nullptr;
    const int*   len = nullptr;
    const int*   tgi = nullptr;
    for (int i = 0; i < n_in; i++) {
        switch (in_sizes[i]) {
            case 33554432: pot = (const float*)d_in[i]; break;
            case 1024:     trn = (const float*)d_in[i]; break;
            case 2048:     len = (const int*)d_in[i];   break;
            case 1048576:  tgi = (const int*)d_in[i];   break;
            default: break;
        }
    }
    float* out = (float*)d_out;
    crf_kernel<<<BB, 32>>>(pot, trn, len, tgi, out);
    (void)out_size;
}

// round 4
// speedup vs baseline: 1.0635x; 1.0635x over previous
#include <cuda_runtime.h>
#include <cuda_bf16.h>

#define BB 2048
#define TT 512
#define KK 32
#define NEG_INF (-3.4e38f)

// One warp per batch item; lane = current tag k.
// tc[j] = trans[j][k] (column k); ec[j] = exp(trans[j][k]).
// Forward normalization uses a warp-uniform offset mcur = previous step's
// aF[lane 0] (broadcast via the smem buffer we already write) instead of an
// exact warp max: the final logsumexp re-normalizes exactly, and
// |aF - mcur| is bounded by the per-step lane spread (O(10)), fp32-safe.
__global__ __launch_bounds__(32) void crf_kernel(
    const float* __restrict__ pot,     // [B,T,K]
    const float* __restrict__ trans,   // [K,K]
    const int*   __restrict__ lens,    // [B]
    const int*   __restrict__ tagidx,  // [B,T]
    float*       __restrict__ out)     // [B*T] tags, [B] best, [B] loglik
{
    const int b    = blockIdx.x;
    const int lane = threadIdx.x;

    __shared__ unsigned char bp_sm[TT * KK];
    __shared__ __align__(16) float aVbuf[2][KK];
    __shared__ __align__(16) float pXbuf[2][KK];
    __shared__ __align__(16) float aFbuf[2][KK];

    // transitions column k into registers (coalesced) + exp
    float tc[KK], ec[KK];
#pragma unroll
    for (int j = 0; j < KK; j++) {
        float v = trans[j * KK + lane];
        tc[j] = v;
        ec[j] = __expf(v);
    }

    const int len = lens[b];
    const float* pb = pot + (size_t)b * TT * KK;

    float aV = pb[lane];
    float aF = aV;
    float mcur = __shfl_sync(0xffffffffu, aF, 0);

    // prefetch ring, depth 4 (rows 1..4 always in-bounds, TT=512)
    float q0 = pb[1 * KK + lane];
    float q1 = pb[2 * KK + lane];
    float q2 = pb[3 * KK + lane];
    float q3 = pb[4 * KK + lane];

    auto step = [&](float pt, int t, int buf) {
        float pexp = __expf(aF - mcur);
        aVbuf[buf][lane] = aV;
        pXbuf[buf][lane] = pexp;
        aFbuf[buf][lane] = aF;
        __syncwarp();
        const float4* a4 = (const float4*)aVbuf[buf];
        const float4* p4 = (const float4*)pXbuf[buf];

        // fused max+argmax (4 ILP chains; strict > keeps first index in-chain)
        float m0 = NEG_INF, m1 = NEG_INF, m2 = NEG_INF, m3 = NEG_INF;
        int   i0 = 0, i1 = 0, i2 = 0, i3 = 0;
        float s0 = 0.f, s1 = 0.f, s2 = 0.f, s3 = 0.f;
#pragma unroll
        for (int q = 0; q < 8; q++) {
            float4 a = a4[q];
            float v0 = a.x + tc[4*q+0]; if (v0 > m0) { m0 = v0; i0 = 4*q+0; }
            float v1 = a.y + tc[4*q+1]; if (v1 > m1) { m1 = v1; i1 = 4*q+1; }
            float v2 = a.z + tc[4*q+2]; if (v2 > m2) { m2 = v2; i2 = 4*q+2; }
            float v3 = a.w + tc[4*q+3]; if (v3 > m3) { m3 = v3; i3 = 4*q+3; }
            float4 p = p4[q];
            s0 += p.x * ec[4*q+0];
            s1 += p.y * ec[4*q+1];
            s2 += p.z * ec[4*q+2];
            s3 += p.w * ec[4*q+3];
        }
        // cross-chain combine: value-tie -> min index (global first-argmax)
        float best = m0; int arg = i0;
        if (m1 > best || (m1 == best && i1 < arg)) { best = m1; arg = i1; }
        if (m2 > best || (m2 == best && i2 < arg)) { best = m2; arg = i2; }
        if (m3 > best || (m3 == best && i3 < arg)) { best = m3; arg = i3; }
        float ssum = (s0 + s1) + (s2 + s3);

        bp_sm[t * KK + lane] = (unsigned char)arg;
        aV = pt + best;
        aF = pt + (mcur + __logf(ssum));
        mcur = aFbuf[buf][0];   // next step's uniform offset (prev aF, lane 0)
    };

    int t = 1;
    for (; t + 3 < len; t += 4) {
        int c4 = min(t + 4, TT - 1), c5 = min(t + 5, TT - 1);
        int c6 = min(t + 6, TT - 1), c7 = min(t + 7, TT - 1);
        float n0 = pb[c4 * KK + lane];
        float n1 = pb[c5 * KK + lane];
        float n2 = pb[c6 * KK + lane];
        float n3 = pb[c7 * KK + lane];
        step(q0, t + 0, 1);
        step(q1, t + 1, 0);
        step(q2, t + 2, 1);
        step(q3, t + 3, 0);
        q0 = n0; q1 = n1; q2 = n2; q3 = n3;
    }
    if (t < len) { step(q0, t, 1); t++; }
    if (t < len) { step(q1, t, 0); t++; }
    if (t < len) { step(q2, t, 1); }
    __syncwarp();

    // ---- Viterbi terminal: best_score + last_tag (first max index) ----
    float mv = aV;
#pragma unroll
    for (int s = 16; s; s >>= 1)
        mv = fmaxf(mv, __shfl_xor_sync(0xffffffffu, mv, s));
    unsigned msk = __ballot_sync(0xffffffffu, aV == mv);
    int last_tag = __ffs(msk) - 1;

    // ---- log partition: exact logsumexp over final forward alpha ----
    float mf = aF;
#pragma unroll
    for (int s = 16; s; s >>= 1)
        mf = fmaxf(mf, __shfl_xor_sync(0xffffffffu, mf, s));
    float ex = __expf(aF - mf);
#pragma unroll
    for (int s = 16; s; s >>= 1)
        ex += __shfl_xor_sync(0xffffffffu, ex, s);
    float log_norm = mf + __logf(ex);

    // ---- decode tags: padded tail is last_tag (identity backpointers) ----
    float* otags = out + (size_t)b * TT;
    for (int tt = lane; tt < TT; tt += 32)
        if (tt >= len - 1)
            otags[tt] = (float)last_tag;

    if (lane == 0) {
        int tg = last_tag;
        for (int tt = len - 1; tt >= 1; tt--) {
            tg = bp_sm[tt * KK + tg];
            otags[tt - 1] = (float)tg;
        }
    }

    // ---- gold sequence score ----
    const int* ti = tagidx + (size_t)b * TT;
    float acc = 0.f;
    for (int tt = lane; tt < TT; tt += 32) {
        int tg = ti[tt];
        if (tt < len)
            acc += pb[tt * KK + tg];
        if (tt < len - 1)
            acc += trans[tg * KK + ti[tt + 1]];
    }
#pragma unroll
    for (int s = 16; s; s >>= 1)
        acc += __shfl_xor_sync(0xffffffffu, acc, s);

    if (lane == 0) {
        out[(size_t)BB * TT + b]      = mv;               // best_score
        out[(size_t)BB * TT + BB + b] = acc - log_norm;   // log_likelihood
    }
}

extern "C" void kernel_launch(void* const* d_in, const int* in_sizes, int n_in,
                              void* d_out, int out_size) {
    const float* pot = nullptr;
    const float* trn = nullptr;
    const int*   len = nullptr;
    const int*   tgi = nullptr;
    for (int i = 0; i < n_in; i++) {
        switch (in_sizes[i]) {
            case 33554432: pot = (const float*)d_in[i]; break;
            case 1024:     trn = (const float*)d_in[i]; break;
            case 2048:     len = (const int*)d_in[i];   break;
            case 1048576:  tgi = (const int*)d_in[i];   break;
            default: break;
        }
    }
    float* out = (float*)d_out;
    crf_kernel<<<BB, 32>>>(pot, trn, len, tgi, out);
    (void)out_size;
}